// round 2
// baseline (speedup 1.0000x reference)
#include <cuda_runtime.h>

#define BATCH   32768
#define SEQ     200
#define NTHREADS 128
#define NBLOCKS (BATCH / NTHREADS)

// ---------------- scratch (static __device__, no allocation) ----------------
// t-major layouts for coalesced access: [feature][batch]
__device__ float g_Hh[4 * SEQ * BATCH];     // layer-1 h of RNN0 (H channel), [4t+k][b]
__device__ float g_Lh[4 * SEQ * BATCH];     // layer-1 h of RNN1 (L channel)
__device__ float g_other[40 * BATCH];       // x_flat @ Wp^T + bp, [j][b]

// ---------------- fast activations (accurate to ~1e-6 rel) ----------------
__device__ __forceinline__ float sigf(float x) {
    return __fdividef(1.0f, 1.0f + __expf(-x));
}
__device__ __forceinline__ float tanhfast(float x) {
    // 1 - 2/(e^{2x}+1): safe at +/-inf (-> +/-1), 2 MUFU ops
    return 1.0f - __fdividef(2.0f, __expf(2.0f * x) + 1.0f);
}

// ---------------- LSTM cell steps (gate order i,f,g,o; H=4) ----------------
// layer-0: scalar input. sw layout: [0:16) wih, [16:80) whh (j*4+k), [80:96) bias
__device__ __forceinline__ void step_l0(const float* __restrict__ sw, float xin,
                                        float* h, float* c) {
    float g[16];
#pragma unroll
    for (int j = 0; j < 16; j++) {
        float v = fmaf(xin, sw[j], sw[80 + j]);
        v = fmaf(h[0], sw[16 + 4 * j + 0], v);
        v = fmaf(h[1], sw[16 + 4 * j + 1], v);
        v = fmaf(h[2], sw[16 + 4 * j + 2], v);
        v = fmaf(h[3], sw[16 + 4 * j + 3], v);
        g[j] = v;
    }
#pragma unroll
    for (int k = 0; k < 4; k++) {
        float cn = sigf(g[4 + k]) * c[k] + sigf(g[k]) * tanhfast(g[8 + k]);
        c[k] = cn;
        h[k] = sigf(g[12 + k]) * tanhfast(cn);
    }
}
// layer-1: 4-vector input. sw layout: [0:64) wih1, [64:128) whh1, [128:144) bias
__device__ __forceinline__ void step_l1(const float* __restrict__ sw, const float* hin,
                                        float* h, float* c) {
    float g[16];
#pragma unroll
    for (int j = 0; j < 16; j++) {
        float v = sw[128 + j];
#pragma unroll
        for (int k = 0; k < 4; k++) v = fmaf(hin[k], sw[4 * j + k], v);
#pragma unroll
        for (int k = 0; k < 4; k++) v = fmaf(h[k], sw[64 + 4 * j + k], v);
        g[j] = v;
    }
#pragma unroll
    for (int k = 0; k < 4; k++) {
        float cn = sigf(g[4 + k]) * c[k] + sigf(g[k]) * tanhfast(g[8 + k]);
        c[k] = cn;
        h[k] = sigf(g[12 + k]) * tanhfast(cn);
    }
}

// ================= Kernel 1: LSTMs + 'other' projection =================
// One thread per sample. x tiles staged through smem for coalesced reads.
__global__ __launch_bounds__(NTHREADS) void lstm_kernel(
    const float* __restrict__ x,
    const float* __restrict__ w0ih0, const float* __restrict__ w0hh0,
    const float* __restrict__ b0ih0, const float* __restrict__ b0hh0,
    const float* __restrict__ w0ih1, const float* __restrict__ w0hh1,
    const float* __restrict__ b0ih1, const float* __restrict__ b0hh1,
    const float* __restrict__ w1ih0, const float* __restrict__ w1hh0,
    const float* __restrict__ b1ih0, const float* __restrict__ b1hh0,
    const float* __restrict__ w1ih1, const float* __restrict__ w1hh1,
    const float* __restrict__ b1ih1, const float* __restrict__ b1hh1,
    const float* __restrict__ Wp, const float* __restrict__ bp)
{
    // per-RNN weight block: [0:96) layer0 (wih16,whh64,bias16), [96:240) layer1
    __shared__ float sW[2][240];
    __shared__ float sXH[NTHREADS][25];  // stride 25: gcd(25,32)=1 -> conflict-free
    __shared__ float sXL[NTHREADS][25];

    const int tid = threadIdx.x;
    const int b0 = blockIdx.x * NTHREADS;
    const int b = b0 + tid;

    if (tid < 16) {
        sW[0][tid]       = w0ih0[tid];
        sW[0][80 + tid]  = b0ih0[tid] + b0hh0[tid];
        sW[0][224 + tid] = b0ih1[tid] + b0hh1[tid];
        sW[1][tid]       = w1ih0[tid];
        sW[1][80 + tid]  = b1ih0[tid] + b1hh0[tid];
        sW[1][224 + tid] = b1ih1[tid] + b1hh1[tid];
    } else if (tid < 80) {
        int i = tid - 16;
        sW[0][16 + i]  = w0hh0[i]; sW[0][96 + i] = w0ih1[i]; sW[0][160 + i] = w0hh1[i];
        sW[1][16 + i]  = w1hh0[i]; sW[1][96 + i] = w1ih1[i]; sW[1][160 + i] = w1hh1[i];
    }

    float hH0[4], cH0[4], hH1[4], cH1[4];
    float hL0[4], cL0[4], hL1[4], cL1[4];
#pragma unroll
    for (int k = 0; k < 4; k++) {
        hH0[k] = cH0[k] = hH1[k] = cH1[k] = 0.0f;
        hL0[k] = cL0[k] = hL1[k] = cL1[k] = 0.0f;
    }
    float accO[40];
#pragma unroll
    for (int j = 0; j < 40; j++) accO[j] = __ldg(&bp[j]);

    for (int tile = 0; tile < 8; ++tile) {      // 8 tiles x 25 steps = 200
        __syncthreads();                        // weights visible / prev compute done
#pragma unroll
        for (int i = tid; i < NTHREADS * 25; i += NTHREADS) {
            int s = i / 25, tt = i % 25;
            size_t base = (size_t)(b0 + s) * (2 * SEQ) + tile * 25 + tt;
            sXH[s][tt] = x[base];
            sXL[s][tt] = x[base + SEQ];
        }
        __syncthreads();
        for (int tt = 0; tt < 25; ++tt) {
            int t = tile * 25 + tt;
            float xh = sXH[tid][tt];
            float xl = sXL[tid][tt];

            step_l0(&sW[0][0],  xh,  hH0, cH0);
            step_l1(&sW[0][96], hH0, hH1, cH1);
            step_l0(&sW[1][0],  xl,  hL0, cL0);
            step_l1(&sW[1][96], hL0, hL1, cL1);

#pragma unroll
            for (int k = 0; k < 4; k++) {
                g_Hh[(size_t)(4 * t + k) * BATCH + b] = hH1[k];
                g_Lh[(size_t)(4 * t + k) * BATCH + b] = hL1[k];
            }
            // other += xh*Wp[:,t] + xl*Wp[:,200+t]   (uniform weight loads -> L1 broadcast)
#pragma unroll
            for (int j = 0; j < 40; j++) {
                float a = fmaf(xh, __ldg(&Wp[j * 400 + t]), accO[j]);
                accO[j] = fmaf(xl, __ldg(&Wp[j * 400 + SEQ + t]), a);
            }
        }
    }
#pragma unroll
    for (int j = 0; j < 40; j++) g_other[(size_t)j * BATCH + b] = accO[j];
}

// ================= Kernel 2: dense head =================
// Hf/Lf computed in 8 chunks of 32 outputs, folded into acc1[80] on the fly
// (avoids ever holding 256 features in registers).
__global__ __launch_bounds__(NTHREADS) void head_kernel(
    const float* __restrict__ WH, const float* __restrict__ bHv,
    const float* __restrict__ WL, const float* __restrict__ bLv,
    const float* __restrict__ W1, const float* __restrict__ b1,
    const float* __restrict__ W2, const float* __restrict__ b2,
    const float* __restrict__ W3, const float* __restrict__ b3,
    float* __restrict__ out)
{
    const int b = blockIdx.x * NTHREADS + threadIdx.x;

    float acc1[80];
#pragma unroll
    for (int i = 0; i < 80; i++) acc1[i] = __ldg(&b1[i]);

#pragma unroll 1
    for (int r = 0; r < 2; r++) {
        const float* __restrict__ hh = (r == 0) ? g_Hh : g_Lh;
        const float* __restrict__ W  = (r == 0) ? WH : WL;
        const float* __restrict__ bb = (r == 0) ? bHv : bLv;
#pragma unroll 1
        for (int cch = 0; cch < 4; ++cch) {
            float acc[32];
#pragma unroll
            for (int j = 0; j < 32; j++) acc[j] = __ldg(&bb[32 * cch + j]);
            const float* wbase = W + (size_t)(32 * cch) * 800;
#pragma unroll 2
            for (int t4 = 0; t4 < 200; ++t4) {
                float hv0 = hh[(size_t)(4 * t4 + 0) * BATCH + b];
                float hv1 = hh[(size_t)(4 * t4 + 1) * BATCH + b];
                float hv2 = hh[(size_t)(4 * t4 + 2) * BATCH + b];
                float hv3 = hh[(size_t)(4 * t4 + 3) * BATCH + b];
#pragma unroll
                for (int j = 0; j < 32; j++) {
                    float4 w = __ldg(reinterpret_cast<const float4*>(
                        wbase + (size_t)j * 800 + 4 * t4));
                    float a = acc[j];
                    a = fmaf(hv0, w.x, a);
                    a = fmaf(hv1, w.y, a);
                    a = fmaf(hv2, w.z, a);
                    acc[j] = fmaf(hv3, w.w, a);
                }
            }
#pragma unroll
            for (int j = 0; j < 32; j++) acc[j] = tanhfast(acc[j]);
            // fold Hf/Lf chunk into z1 pre-activation via W1 columns
            const int colbase = r * 128 + 32 * cch;
#pragma unroll
            for (int i = 0; i < 80; i++) {
                const float4* w4 = reinterpret_cast<const float4*>(
                    W1 + (size_t)i * 256 + colbase);
                float s = acc1[i];
#pragma unroll
                for (int j4 = 0; j4 < 8; j4++) {
                    float4 w = __ldg(&w4[j4]);
                    s = fmaf(acc[4 * j4 + 0], w.x, s);
                    s = fmaf(acc[4 * j4 + 1], w.y, s);
                    s = fmaf(acc[4 * j4 + 2], w.z, s);
                    s = fmaf(acc[4 * j4 + 3], w.w, s);
                }
                acc1[i] = s;
            }
        }
    }
    // z1 = tanh(.)
#pragma unroll
    for (int i = 0; i < 80; i++) acc1[i] = tanhfast(acc1[i]);

    // z2 -> fold straight into final dot (no z2 array needed)
    float s3 = __ldg(&b3[0]);
#pragma unroll 1
    for (int i = 0; i < 40; i++) {
        float s = __ldg(&b2[i]);
        const float4* w4 = reinterpret_cast<const float4*>(W2 + (size_t)i * 80);
#pragma unroll
        for (int j4 = 0; j4 < 20; j4++) {
            float4 w = __ldg(&w4[j4]);
            s = fmaf(acc1[4 * j4 + 0], w.x, s);
            s = fmaf(acc1[4 * j4 + 1], w.y, s);
            s = fmaf(acc1[4 * j4 + 2], w.z, s);
            s = fmaf(acc1[4 * j4 + 3], w.w, s);
        }
        s3 = fmaf(tanhfast(s), __ldg(&W3[i]), s3);
    }
#pragma unroll 8
    for (int k = 0; k < 40; k++) {
        s3 = fmaf(g_other[(size_t)k * BATCH + b], __ldg(&W3[40 + k]), s3);
    }
    out[b] = sigf(s3);
}

// ================= launch =================
extern "C" void kernel_launch(void* const* d_in, const int* in_sizes, int n_in,
                              void* d_out, int out_size)
{
    (void)in_sizes; (void)n_in; (void)out_size;
    const float* x     = (const float*)d_in[0];
    const float* w0ih0 = (const float*)d_in[1];
    const float* w0hh0 = (const float*)d_in[2];
    const float* b0ih0 = (const float*)d_in[3];
    const float* b0hh0 = (const float*)d_in[4];
    const float* w0ih1 = (const float*)d_in[5];
    const float* w0hh1 = (const float*)d_in[6];
    const float* b0ih1 = (const float*)d_in[7];
    const float* b0hh1 = (const float*)d_in[8];
    const float* w1ih0 = (const float*)d_in[9];
    const float* w1hh0 = (const float*)d_in[10];
    const float* b1ih0 = (const float*)d_in[11];
    const float* b1hh0 = (const float*)d_in[12];
    const float* w1ih1 = (const float*)d_in[13];
    const float* w1hh1 = (const float*)d_in[14];
    const float* b1ih1 = (const float*)d_in[15];
    const float* b1hh1 = (const float*)d_in[16];
    const float* Wp    = (const float*)d_in[17];
    const float* bp    = (const float*)d_in[18];
    const float* WH    = (const float*)d_in[19];
    const float* bH    = (const float*)d_in[20];
    const float* WL    = (const float*)d_in[21];
    const float* bL    = (const float*)d_in[22];
    const float* W1    = (const float*)d_in[23];
    const float* b1    = (const float*)d_in[24];
    const float* W2    = (const float*)d_in[25];
    const float* b2    = (const float*)d_in[26];
    const float* W3    = (const float*)d_in[27];
    const float* b3    = (const float*)d_in[28];
    float* out = (float*)d_out;

    lstm_kernel<<<NBLOCKS, NTHREADS>>>(x,
        w0ih0, w0hh0, b0ih0, b0hh0, w0ih1, w0hh1, b0ih1, b0hh1,
        w1ih0, w1hh0, b1ih0, b1hh0, w1ih1, w1hh1, b1ih1, b1hh1,
        Wp, bp);
    head_kernel<<<NBLOCKS, NTHREADS>>>(WH, bH, WL, bL, W1, b1, W2, b2, W3, b3, out);
}

// round 3
// speedup vs baseline: 1.9938x; 1.9938x over previous
#include <cuda_runtime.h>

#define BATCH    32768
#define SEQ      200
#define NTHREADS 128
#define NBLOCKS  (BATCH / NTHREADS)

// ---------------- scratch (static __device__, no allocation) ----------------
__device__ float g_Hh[4 * SEQ * BATCH];   // layer-1 h of H RNN, [4t+k][b]
__device__ float g_Lh[4 * SEQ * BATCH];   // layer-1 h of L RNN
__device__ float g_F[256 * BATCH];        // tanh features [Hf(128);Lf(128)] x [b]
__device__ float g_dot[2 * BATCH];        // x·u partial dots (H part, L part)
__device__ float g_u[400];                // Wp^T @ W3[40:80]
__device__ float g_c0[1];                 // b3 + bp·W3[40:80]

// ---------------- f32x2 packed helpers (Blackwell) ----------------
typedef unsigned long long ull;
__device__ __forceinline__ ull pk(float a, float b) {
    ull r; asm("mov.b64 %0, {%1,%2};" : "=l"(r) : "f"(a), "f"(b)); return r;
}
__device__ __forceinline__ float2 upk(ull v) {
    float2 f; asm("mov.b64 {%0,%1}, %2;" : "=f"(f.x), "=f"(f.y) : "l"(v)); return f;
}
__device__ __forceinline__ ull fma2(ull a, ull b, ull c) {
    ull d; asm("fma.rn.f32x2 %0, %1, %2, %3;" : "=l"(d) : "l"(a), "l"(b), "l"(c));
    return d;
}

// ---------------- fast activations (accurate to ~1e-6 rel) ----------------
__device__ __forceinline__ float sigf(float x) {
    return __fdividef(1.0f, 1.0f + __expf(-x));
}
__device__ __forceinline__ float tanhfast(float x) {
    return 1.0f - __fdividef(2.0f, __expf(2.0f * x) + 1.0f);
}

// ================= Kernel 0: fold 'other' path into a 400-vector =================
__global__ void prep_kernel(const float* __restrict__ Wp, const float* __restrict__ bp,
                            const float* __restrict__ W3, const float* __restrict__ b3)
{
    int k = blockIdx.x * blockDim.x + threadIdx.x;
    if (k < 400) {
        float s = 0.0f;
#pragma unroll
        for (int j = 0; j < 40; j++) s = fmaf(W3[40 + j], Wp[j * 400 + k], s);
        g_u[k] = s;
    }
    if (k == 400) {
        float s = b3[0];
#pragma unroll
        for (int j = 0; j < 40; j++) s = fmaf(W3[40 + j], bp[j], s);
        g_c0[0] = s;
    }
}

// ================= LSTM cell (scalar activations; H=4) =================
__device__ __forceinline__ void cell_update(const float* g, float* h, float* c) {
#pragma unroll
    for (int k = 0; k < 4; k++) {
        float cn = sigf(g[4 + k]) * c[k] + sigf(g[k]) * tanhfast(g[8 + k]);
        c[k] = cn;
        h[k] = sigf(g[12 + k]) * tanhfast(cn);
    }
}

// ================= Kernel 1: 2-layer LSTM, one channel per block =================
// grid (NBLOCKS, 2): blockIdx.y = 0 -> H (r0 weights), 1 -> L (r1 weights)
__global__ __launch_bounds__(NTHREADS) void lstm_kernel(
    const float* __restrict__ x,
    const float* __restrict__ w0ih0, const float* __restrict__ w0hh0,
    const float* __restrict__ b0ih0, const float* __restrict__ b0hh0,
    const float* __restrict__ w0ih1, const float* __restrict__ w0hh1,
    const float* __restrict__ b0ih1, const float* __restrict__ b0hh1,
    const float* __restrict__ w1ih0, const float* __restrict__ w1hh0,
    const float* __restrict__ b1ih0, const float* __restrict__ b1hh0,
    const float* __restrict__ w1ih1, const float* __restrict__ w1hh1,
    const float* __restrict__ b1ih1, const float* __restrict__ b1hh1)
{
    __shared__ ull sWih0[8], sB0[8], sB1[8];
    __shared__ ull sWhh0[32], sWih1[32], sWhh1[32];   // layout [k][pair] = k*8+p
    __shared__ float sX[NTHREADS][25];                // gcd(25,32)=1 -> conflict-free

    const int tid = threadIdx.x;
    const int ch  = blockIdx.y;
    const int b0  = blockIdx.x * NTHREADS;
    const int b   = b0 + tid;

    const float* wih0 = ch ? w1ih0 : w0ih0;
    const float* whh0 = ch ? w1hh0 : w0hh0;
    const float* bi0  = ch ? b1ih0 : b0ih0;
    const float* bh0  = ch ? b1hh0 : b0hh0;
    const float* wih1 = ch ? w1ih1 : w0ih1;
    const float* whh1 = ch ? w1hh1 : w0hh1;
    const float* bi1  = ch ? b1ih1 : b0ih1;
    const float* bh1  = ch ? b1hh1 : b0hh1;
    float* __restrict__ hout = ch ? g_Lh : g_Hh;

    if (tid < 8) {
        int p = tid;
        sWih0[p] = pk(wih0[2 * p], wih0[2 * p + 1]);
        sB0[p]   = pk(bi0[2 * p] + bh0[2 * p], bi0[2 * p + 1] + bh0[2 * p + 1]);
        sB1[p]   = pk(bi1[2 * p] + bh1[2 * p], bi1[2 * p + 1] + bh1[2 * p + 1]);
    }
    if (tid < 32) {
        int k = tid >> 3, p = tid & 7;
        sWhh0[tid] = pk(whh0[(2 * p) * 4 + k], whh0[(2 * p + 1) * 4 + k]);
        sWih1[tid] = pk(wih1[(2 * p) * 4 + k], wih1[(2 * p + 1) * 4 + k]);
        sWhh1[tid] = pk(whh1[(2 * p) * 4 + k], whh1[(2 * p + 1) * 4 + k]);
    }

    float h0[4], c0a[4], h1[4], c1[4];
#pragma unroll
    for (int k = 0; k < 4; k++) { h0[k] = c0a[k] = h1[k] = c1[k] = 0.0f; }
    float dacc = 0.0f;
    const float* uvec = g_u + ch * SEQ;

    for (int tile = 0; tile < 8; ++tile) {
        __syncthreads();
#pragma unroll
        for (int i = tid; i < NTHREADS * 25; i += NTHREADS) {
            int s = i / 25, tt = i % 25;
            sX[s][tt] = x[(size_t)(b0 + s) * (2 * SEQ) + ch * SEQ + tile * 25 + tt];
        }
        __syncthreads();

        for (int tt = 0; tt < 25; ++tt) {
            const int t = tile * 25 + tt;
            const float xh = sX[tid][tt];
            dacc = fmaf(xh, __ldg(&uvec[t]), dacc);

            // ---- layer 0 (scalar input) ----
            ull v[8];
            {
                ull x2 = pk(xh, xh);
#pragma unroll
                for (int p = 0; p < 8; p++) v[p] = fma2(x2, sWih0[p], sB0[p]);
#pragma unroll
                for (int k = 0; k < 4; k++) {
                    ull h2 = pk(h0[k], h0[k]);
#pragma unroll
                    for (int p = 0; p < 8; p++) v[p] = fma2(h2, sWhh0[k * 8 + p], v[p]);
                }
            }
            float g[16];
#pragma unroll
            for (int p = 0; p < 8; p++) { float2 f = upk(v[p]); g[2 * p] = f.x; g[2 * p + 1] = f.y; }
            cell_update(g, h0, c0a);

            // ---- layer 1 (4-vector input) ----
#pragma unroll
            for (int p = 0; p < 8; p++) v[p] = sB1[p];
#pragma unroll
            for (int k = 0; k < 4; k++) {
                ull h2 = pk(h0[k], h0[k]);
#pragma unroll
                for (int p = 0; p < 8; p++) v[p] = fma2(h2, sWih1[k * 8 + p], v[p]);
            }
#pragma unroll
            for (int k = 0; k < 4; k++) {
                ull h2 = pk(h1[k], h1[k]);
#pragma unroll
                for (int p = 0; p < 8; p++) v[p] = fma2(h2, sWhh1[k * 8 + p], v[p]);
            }
#pragma unroll
            for (int p = 0; p < 8; p++) { float2 f = upk(v[p]); g[2 * p] = f.x; g[2 * p + 1] = f.y; }
            cell_update(g, h1, c1);

#pragma unroll
            for (int k = 0; k < 4; k++)
                hout[(size_t)(4 * t + k) * BATCH + b] = h1[k];
        }
    }
    g_dot[ch * BATCH + b] = dacc;
}

// ================= Kernel 2: feature GEMM  tanh(h[800] @ W^T[64-chunk]) =================
// grid (NBLOCKS, 2, 2): y = 64-chunk (0/1), z = rnn (0=H, 1=L)
__global__ __launch_bounds__(NTHREADS) void feat_kernel(
    const float* __restrict__ WH, const float* __restrict__ bHv,
    const float* __restrict__ WL, const float* __restrict__ bLv)
{
    __shared__ __align__(16) float sW[100 * 68];   // [k in 0..99][j in 0..63], pad 68

    const int tid = threadIdx.x;
    const int b   = blockIdx.x * NTHREADS + tid;
    const int cch = blockIdx.y;
    const int r   = blockIdx.z;

    const float* __restrict__ W  = r ? WL : WH;
    const float* __restrict__ bb = r ? bLv : bHv;
    const float* __restrict__ hh = r ? g_Lh : g_Hh;
    const int jb = cch * 64;
    const int fb = r * 128 + jb;

    ull acc[32];
#pragma unroll
    for (int p = 0; p < 32; p++)
        acc[p] = pk(__ldg(&bb[jb + 2 * p]), __ldg(&bb[jb + 2 * p + 1]));

    for (int tile = 0; tile < 8; ++tile) {
        __syncthreads();
        // stage 64x100 weight tile, pair-interleaved ([k][j] is already pair order)
        for (int idx = tid; idx < 6400; idx += NTHREADS) {
            int j = idx / 100, k = idx % 100;
            sW[k * 68 + j] = __ldg(&W[(size_t)(jb + j) * 800 + tile * 100 + k]);
        }
        __syncthreads();

#pragma unroll 1
        for (int tt = 0; tt < 25; ++tt) {
            const int t4 = tile * 25 + tt;
            const float* hp = hh + (size_t)(4 * t4) * BATCH + b;
            float hv[4];
            hv[0] = __ldg(hp);
            hv[1] = __ldg(hp + BATCH);
            hv[2] = __ldg(hp + 2 * BATCH);
            hv[3] = __ldg(hp + 3 * BATCH);
#pragma unroll
            for (int kk = 0; kk < 4; kk++) {
                ull hd = pk(hv[kk], hv[kk]);
                const ulonglong2* wp =
                    reinterpret_cast<const ulonglong2*>(sW + (tt * 4 + kk) * 68);
#pragma unroll
                for (int m = 0; m < 16; m++) {
                    ulonglong2 w = wp[m];
                    acc[2 * m]     = fma2(hd, w.x, acc[2 * m]);
                    acc[2 * m + 1] = fma2(hd, w.y, acc[2 * m + 1]);
                }
            }
        }
    }
#pragma unroll
    for (int p = 0; p < 32; p++) {
        float2 f = upk(acc[p]);
        g_F[(size_t)(fb + 2 * p) * BATCH + b]     = tanhfast(f.x);
        g_F[(size_t)(fb + 2 * p + 1) * BATCH + b] = tanhfast(f.y);
    }
}

// ================= Kernel 3: combine  256 -> 80 -> 40 -> 1 =================
__global__ __launch_bounds__(NTHREADS) void combine_kernel(
    const float* __restrict__ W1, const float* __restrict__ b1,
    const float* __restrict__ W2, const float* __restrict__ b2,
    const float* __restrict__ W3,
    float* __restrict__ out)
{
    const int b = blockIdx.x * NTHREADS + threadIdx.x;

    float acc1[80];
#pragma unroll
    for (int i = 0; i < 80; i++) acc1[i] = __ldg(&b1[i]);

#pragma unroll 1
    for (int q = 0; q < 64; ++q) {             // feature quads
        const float* fp = g_F + (size_t)(4 * q) * BATCH + b;
        float v0 = __ldg(fp);
        float v1 = __ldg(fp + BATCH);
        float v2 = __ldg(fp + 2 * BATCH);
        float v3 = __ldg(fp + 3 * BATCH);
#pragma unroll
        for (int i = 0; i < 80; i++) {
            float4 w = __ldg(reinterpret_cast<const float4*>(W1 + (size_t)i * 256 + 4 * q));
            float s = acc1[i];
            s = fmaf(v0, w.x, s);
            s = fmaf(v1, w.y, s);
            s = fmaf(v2, w.z, s);
            acc1[i] = fmaf(v3, w.w, s);
        }
    }
#pragma unroll
    for (int i = 0; i < 80; i++) acc1[i] = tanhfast(acc1[i]);

    float s3 = g_c0[0] + g_dot[b] + g_dot[BATCH + b];
#pragma unroll 1
    for (int i = 0; i < 40; i++) {
        float s = __ldg(&b2[i]);
        const float4* w4 = reinterpret_cast<const float4*>(W2 + (size_t)i * 80);
#pragma unroll
        for (int j4 = 0; j4 < 20; j4++) {
            float4 w = __ldg(&w4[j4]);
            s = fmaf(acc1[4 * j4 + 0], w.x, s);
            s = fmaf(acc1[4 * j4 + 1], w.y, s);
            s = fmaf(acc1[4 * j4 + 2], w.z, s);
            s = fmaf(acc1[4 * j4 + 3], w.w, s);
        }
        s3 = fmaf(tanhfast(s), __ldg(&W3[i]), s3);
    }
    out[b] = sigf(s3);
}

// ================= launch =================
extern "C" void kernel_launch(void* const* d_in, const int* in_sizes, int n_in,
                              void* d_out, int out_size)
{
    (void)in_sizes; (void)n_in; (void)out_size;
    const float* x     = (const float*)d_in[0];
    const float* w0ih0 = (const float*)d_in[1];
    const float* w0hh0 = (const float*)d_in[2];
    const float* b0ih0 = (const float*)d_in[3];
    const float* b0hh0 = (const float*)d_in[4];
    const float* w0ih1 = (const float*)d_in[5];
    const float* w0hh1 = (const float*)d_in[6];
    const float* b0ih1 = (const float*)d_in[7];
    const float* b0hh1 = (const float*)d_in[8];
    const float* w1ih0 = (const float*)d_in[9];
    const float* w1hh0 = (const float*)d_in[10];
    const float* b1ih0 = (const float*)d_in[11];
    const float* b1hh0 = (const float*)d_in[12];
    const float* w1ih1 = (const float*)d_in[13];
    const float* w1hh1 = (const float*)d_in[14];
    const float* b1ih1 = (const float*)d_in[15];
    const float* b1hh1 = (const float*)d_in[16];
    const float* Wp    = (const float*)d_in[17];
    const float* bp    = (const float*)d_in[18];
    const float* WH    = (const float*)d_in[19];
    const float* bH    = (const float*)d_in[20];
    const float* WL    = (const float*)d_in[21];
    const float* bL    = (const float*)d_in[22];
    const float* W1    = (const float*)d_in[23];
    const float* b1    = (const float*)d_in[24];
    const float* W2    = (const float*)d_in[25];
    const float* b2    = (const float*)d_in[26];
    const float* W3    = (const float*)d_in[27];
    const float* b3    = (const float*)d_in[28];
    float* out = (float*)d_out;

    prep_kernel<<<2, 256>>>(Wp, bp, W3, b3);

    dim3 gl(NBLOCKS, 2);
    lstm_kernel<<<gl, NTHREADS>>>(x,
        w0ih0, w0hh0, b0ih0, b0hh0, w0ih1, w0hh1, b0ih1, b0hh1,
        w1ih0, w1hh0, b1ih0, b1hh0, w1ih1, w1hh1, b1ih1, b1hh1);

    dim3 gf(NBLOCKS, 2, 2);
    feat_kernel<<<gf, NTHREADS>>>(WH, bH, WL, bL);

    combine_kernel<<<NBLOCKS, NTHREADS>>>(W1, b1, W2, b2, W3, out);
}

// round 6
// speedup vs baseline: 2.0946x; 1.0505x over previous
#include <cuda_runtime.h>

#define BATCH    32768
#define SEQ      200
#define NTHREADS 128
#define NBLOCKS  (BATCH / NTHREADS)

// ---------------- scratch (static __device__, no allocation) ----------------
__device__ float4 g_Hh4[SEQ * BATCH];     // layer-1 h of H RNN, [t][b] = {h0,h1,h2,h3}
__device__ float4 g_Lh4[SEQ * BATCH];     // layer-1 h of L RNN
__device__ float  g_F[256 * BATCH];       // tanh features [Hf(128);Lf(128)] x [b]
__device__ float  g_dot[2 * BATCH];       // x·u partial dots (H part, L part)
__device__ float  g_u[400];               // Wp^T @ W3[40:80]
__device__ float  g_c0[1];                // b3 + bp·W3[40:80]
__device__ float  g_Wt[2 * 2 * 8 * 100 * 64]; // feat weights [r][cch][tile][k][j]

// ---------------- f32x2 packed helpers (Blackwell) ----------------
typedef unsigned long long ull;
__device__ __forceinline__ ull pk(float a, float b) {
    ull r; asm("mov.b64 %0, {%1,%2};" : "=l"(r) : "f"(a), "f"(b)); return r;
}
__device__ __forceinline__ float2 upk(ull v) {
    float2 f; asm("mov.b64 {%0,%1}, %2;" : "=f"(f.x), "=f"(f.y) : "l"(v)); return f;
}
__device__ __forceinline__ ull fma2(ull a, ull b, ull c) {
    ull d; asm("fma.rn.f32x2 %0, %1, %2, %3;" : "=l"(d) : "l"(a), "l"(b), "l"(c));
    return d;
}

// ---------------- activations ----------------
// HW tanh (1 MUFU op, ~1e-4 max err) — used ONLY in the LSTM recurrence
__device__ __forceinline__ float tanha(float x) {
    float y; asm("tanh.approx.f32 %0, %1;" : "=f"(y) : "f"(x)); return y;
}
__device__ __forceinline__ float siga(float x) {
    return fmaf(tanha(0.5f * x), 0.5f, 0.5f);
}
// accurate versions (~1e-7) — used in the head
__device__ __forceinline__ float sigf(float x) {
    return __fdividef(1.0f, 1.0f + __expf(-x));
}
__device__ __forceinline__ float tanhfast(float x) {
    return 1.0f - __fdividef(2.0f, __expf(2.0f * x) + 1.0f);
}

// ================= prep A: fold 'other' path into a 400-vector =================
__global__ void prep_u_kernel(const float* __restrict__ Wp, const float* __restrict__ bp,
                              const float* __restrict__ W3, const float* __restrict__ b3)
{
    int k = blockIdx.x * blockDim.x + threadIdx.x;
    if (k < 400) {
        float s = 0.0f;
#pragma unroll
        for (int j = 0; j < 40; j++) s = fmaf(W3[40 + j], Wp[j * 400 + k], s);
        g_u[k] = s;
    }
    if (k == 400) {
        float s = b3[0];
#pragma unroll
        for (int j = 0; j < 40; j++) s = fmaf(W3[40 + j], bp[j], s);
        g_c0[0] = s;
    }
}

// ================= prep B: transpose feat weights for conflict-free staging ======
// g_Wt[((r*2+cch)*8+tile)*6400 + k*64 + j] = W_r[(cch*64+j)*800 + tile*100 + k]
__global__ void prep_w_kernel(const float* __restrict__ WH, const float* __restrict__ WL)
{
    int idx = blockIdx.x * blockDim.x + threadIdx.x;   // 0 .. 204799
    if (idx >= 2 * 2 * 8 * 6400) return;
    int j    = idx & 63;
    int k    = (idx >> 6) % 100;
    int tile = (idx / 6400) & 7;
    int cch  = (idx / (6400 * 8)) & 1;
    int r    = idx / (6400 * 16);
    const float* W = r ? WL : WH;
    g_Wt[idx] = W[(size_t)(cch * 64 + j) * 800 + tile * 100 + k];
}

// ================= LSTM cell (H=4, gate order i,f,g,o) =================
__device__ __forceinline__ void cell_update(const float* g, float* h, float* c) {
#pragma unroll
    for (int k = 0; k < 4; k++) {
        float cn = siga(g[4 + k]) * c[k] + siga(g[k]) * tanha(g[8 + k]);
        c[k] = cn;
        h[k] = siga(g[12 + k]) * tanha(cn);
    }
}

// ================= Kernel 1: 2-layer LSTM, one channel per block =================
// grid (NBLOCKS, 2): blockIdx.y = 0 -> H (r0 weights), 1 -> L (r1 weights)
__global__ __launch_bounds__(NTHREADS) void lstm_kernel(
    const float* __restrict__ x,
    const float* __restrict__ w0ih0, const float* __restrict__ w0hh0,
    const float* __restrict__ b0ih0, const float* __restrict__ b0hh0,
    const float* __restrict__ w0ih1, const float* __restrict__ w0hh1,
    const float* __restrict__ b0ih1, const float* __restrict__ b0hh1,
    const float* __restrict__ w1ih0, const float* __restrict__ w1hh0,
    const float* __restrict__ b1ih0, const float* __restrict__ b1hh0,
    const float* __restrict__ w1ih1, const float* __restrict__ w1hh1,
    const float* __restrict__ b1ih1, const float* __restrict__ b1hh1)
{
    __shared__ ull sWih0[8], sB0[8], sB1[8];
    __shared__ ull sWhh0[32], sWih1[32], sWhh1[32];   // [k][pair] = k*8+p
    __shared__ float sX[NTHREADS][25];                // gcd(25,32)=1 -> conflict-free

    const int tid = threadIdx.x;
    const int ch  = blockIdx.y;
    const int b0  = blockIdx.x * NTHREADS;
    const int b   = b0 + tid;

    const float* wih0 = ch ? w1ih0 : w0ih0;
    const float* whh0 = ch ? w1hh0 : w0hh0;
    const float* bi0  = ch ? b1ih0 : b0ih0;
    const float* bh0  = ch ? b1hh0 : b0hh0;
    const float* wih1 = ch ? w1ih1 : w0ih1;
    const float* whh1 = ch ? w1hh1 : w0hh1;
    const float* bi1  = ch ? b1ih1 : b0ih1;
    const float* bh1  = ch ? b1hh1 : b0hh1;
    float4* __restrict__ hout4 = ch ? g_Lh4 : g_Hh4;

    if (tid < 8) {
        int p = tid;
        sWih0[p] = pk(wih0[2 * p], wih0[2 * p + 1]);
        sB0[p]   = pk(bi0[2 * p] + bh0[2 * p], bi0[2 * p + 1] + bh0[2 * p + 1]);
        sB1[p]   = pk(bi1[2 * p] + bh1[2 * p], bi1[2 * p + 1] + bh1[2 * p + 1]);
    }
    if (tid < 32) {
        int k = tid >> 3, p = tid & 7;
        sWhh0[tid] = pk(whh0[(2 * p) * 4 + k], whh0[(2 * p + 1) * 4 + k]);
        sWih1[tid] = pk(wih1[(2 * p) * 4 + k], wih1[(2 * p + 1) * 4 + k]);
        sWhh1[tid] = pk(whh1[(2 * p) * 4 + k], whh1[(2 * p + 1) * 4 + k]);
    }

    float h0[4], c0a[4], h1[4], c1[4];
#pragma unroll
    for (int k = 0; k < 4; k++) { h0[k] = c0a[k] = h1[k] = c1[k] = 0.0f; }
    float dacc = 0.0f;
    const float* uvec = g_u + ch * SEQ;

    for (int tile = 0; tile < 8; ++tile) {
        __syncthreads();
#pragma unroll
        for (int i = tid; i < NTHREADS * 25; i += NTHREADS) {
            int s = i / 25, tt = i % 25;
            sX[s][tt] = x[(size_t)(b0 + s) * (2 * SEQ) + ch * SEQ + tile * 25 + tt];
        }
        __syncthreads();

        for (int tt = 0; tt < 25; ++tt) {
            const int t = tile * 25 + tt;
            const float xh = sX[tid][tt];
            dacc = fmaf(xh, __ldg(&uvec[t]), dacc);

            // ---- layer 0 (scalar input) ----
            ull v[8];
            {
                ull x2 = pk(xh, xh);
#pragma unroll
                for (int p = 0; p < 8; p++) v[p] = fma2(x2, sWih0[p], sB0[p]);
#pragma unroll
                for (int k = 0; k < 4; k++) {
                    ull h2 = pk(h0[k], h0[k]);
#pragma unroll
                    for (int p = 0; p < 8; p++) v[p] = fma2(h2, sWhh0[k * 8 + p], v[p]);
                }
            }
            float g[16];
#pragma unroll
            for (int p = 0; p < 8; p++) { float2 f = upk(v[p]); g[2 * p] = f.x; g[2 * p + 1] = f.y; }
            cell_update(g, h0, c0a);

            // ---- layer 1 (4-vector input) ----
#pragma unroll
            for (int p = 0; p < 8; p++) v[p] = sB1[p];
#pragma unroll
            for (int k = 0; k < 4; k++) {
                ull h2 = pk(h0[k], h0[k]);
#pragma unroll
                for (int p = 0; p < 8; p++) v[p] = fma2(h2, sWih1[k * 8 + p], v[p]);
            }
#pragma unroll
            for (int k = 0; k < 4; k++) {
                ull h2 = pk(h1[k], h1[k]);
#pragma unroll
                for (int p = 0; p < 8; p++) v[p] = fma2(h2, sWhh1[k * 8 + p], v[p]);
            }
#pragma unroll
            for (int p = 0; p < 8; p++) { float2 f = upk(v[p]); g[2 * p] = f.x; g[2 * p + 1] = f.y; }
            cell_update(g, h1, c1);

            hout4[(size_t)t * BATCH + b] = make_float4(h1[0], h1[1], h1[2], h1[3]);
        }
    }
    g_dot[ch * BATCH + b] = dacc;
}

// ================= Kernel 2: feature GEMM  tanh(h[800] @ W^T[64-chunk]) =================
// grid (NBLOCKS, 2, 2): y = 64-chunk (0/1), z = rnn (0=H, 1=L)
__global__ __launch_bounds__(NTHREADS) void feat_kernel(
    const float* __restrict__ bHv, const float* __restrict__ bLv)
{
    __shared__ __align__(16) float sW[6400];      // [k(100)][j(64)], rows 256B-aligned

    const int tid = threadIdx.x;
    const int b   = blockIdx.x * NTHREADS + tid;
    const int cch = blockIdx.y;
    const int r   = blockIdx.z;

    const float* __restrict__ bb  = r ? bLv : bHv;
    const float4* __restrict__ hh4 = r ? g_Lh4 : g_Hh4;
    const int jb = cch * 64;
    const int fb = r * 128 + jb;

    ull acc[32];
#pragma unroll
    for (int p = 0; p < 32; p++)
        acc[p] = pk(__ldg(&bb[jb + 2 * p]), __ldg(&bb[jb + 2 * p + 1]));

    for (int tile = 0; tile < 8; ++tile) {
        __syncthreads();
        const float4* wsrc = reinterpret_cast<const float4*>(
            g_Wt + ((size_t)((r * 2 + cch) * 8 + tile)) * 6400);
#pragma unroll
        for (int i4 = tid; i4 < 1600; i4 += NTHREADS)
            reinterpret_cast<float4*>(sW)[i4] = __ldg(&wsrc[i4]);
        __syncthreads();

#pragma unroll 1
        for (int tt = 0; tt < 25; ++tt) {
            const int t4 = tile * 25 + tt;
            float4 hv = __ldg(&hh4[(size_t)t4 * BATCH + b]);
            float hvk[4] = {hv.x, hv.y, hv.z, hv.w};
#pragma unroll
            for (int kk = 0; kk < 4; kk++) {
                ull hd = pk(hvk[kk], hvk[kk]);
                const ulonglong2* wp =
                    reinterpret_cast<const ulonglong2*>(sW + (tt * 4 + kk) * 64);
#pragma unroll
                for (int m = 0; m < 16; m++) {
                    ulonglong2 w = wp[m];
                    acc[2 * m]     = fma2(hd, w.x, acc[2 * m]);
                    acc[2 * m + 1] = fma2(hd, w.y, acc[2 * m + 1]);
                }
            }
        }
    }
#pragma unroll
    for (int p = 0; p < 32; p++) {
        float2 f = upk(acc[p]);
        g_F[(size_t)(fb + 2 * p) * BATCH + b]     = tanhfast(f.x);
        g_F[(size_t)(fb + 2 * p + 1) * BATCH + b] = tanhfast(f.y);
    }
}

// ================= Kernel 3: combine  256 -> 80 -> 40 -> 1  (4 threads/sample) ====
__global__ __launch_bounds__(NTHREADS) void combine_kernel(
    const float* __restrict__ W1, const float* __restrict__ b1,
    const float* __restrict__ W2, const float* __restrict__ b2,
    const float* __restrict__ W3,
    float* __restrict__ out)
{
    const int tid  = threadIdx.x;
    const int part = tid & 3;                       // which quarter of features
    const int b    = blockIdx.x * 32 + (tid >> 2);  // sample

    float acc1[80];
#pragma unroll
    for (int i = 0; i < 80; i++) acc1[i] = 0.0f;

#pragma unroll 1
    for (int q = 0; q < 16; ++q) {                  // 16 quads = 64 features per lane
        const int f0 = part * 64 + 4 * q;
        const float* fp = g_F + (size_t)f0 * BATCH + b;
        float v0 = __ldg(fp);
        float v1 = __ldg(fp + BATCH);
        float v2 = __ldg(fp + 2 * BATCH);
        float v3 = __ldg(fp + 3 * BATCH);
#pragma unroll
        for (int i = 0; i < 80; i++) {
            float4 w = __ldg(reinterpret_cast<const float4*>(W1 + (size_t)i * 256 + f0));
            float s = acc1[i];
            s = fmaf(v0, w.x, s);
            s = fmaf(v1, w.y, s);
            s = fmaf(v2, w.z, s);
            acc1[i] = fmaf(v3, w.w, s);
        }
    }
    // reduce partial acc1 across the 4-lane group, add bias, tanh
#pragma unroll
    for (int i = 0; i < 80; i++) {
        float s = acc1[i];
        s += __shfl_xor_sync(0xffffffffu, s, 1);
        s += __shfl_xor_sync(0xffffffffu, s, 2);
        acc1[i] = tanhfast(s + __ldg(&b1[i]));
    }

    // each lane handles 10 of the 40 W2 rows, folded into the final dot
    float s3p = 0.0f;
#pragma unroll 1
    for (int r10 = 0; r10 < 10; ++r10) {
        const int i2 = part * 10 + r10;
        float s = __ldg(&b2[i2]);
        const float4* w4 = reinterpret_cast<const float4*>(W2 + (size_t)i2 * 80);
#pragma unroll
        for (int j4 = 0; j4 < 20; j4++) {
            float4 w = __ldg(&w4[j4]);
            s = fmaf(acc1[4 * j4 + 0], w.x, s);
            s = fmaf(acc1[4 * j4 + 1], w.y, s);
            s = fmaf(acc1[4 * j4 + 2], w.z, s);
            s = fmaf(acc1[4 * j4 + 3], w.w, s);
        }
        s3p = fmaf(tanhfast(s), __ldg(&W3[i2]), s3p);
    }
    s3p += __shfl_xor_sync(0xffffffffu, s3p, 1);
    s3p += __shfl_xor_sync(0xffffffffu, s3p, 2);

    if (part == 0)
        out[b] = sigf(s3p + g_c0[0] + g_dot[b] + g_dot[BATCH + b]);
}

// ================= launch =================
extern "C" void kernel_launch(void* const* d_in, const int* in_sizes, int n_in,
                              void* d_out, int out_size)
{
    (void)in_sizes; (void)n_in; (void)out_size;
    const float* x     = (const float*)d_in[0];
    const float* w0ih0 = (const float*)d_in[1];
    const float* w0hh0 = (const float*)d_in[2];
    const float* b0ih0 = (const float*)d_in[3];
    const float* b0hh0 = (const float*)d_in[4];
    const float* w0ih1 = (const float*)d_in[5];
    const float* w0hh1 = (const float*)d_in[6];
    const float* b0ih1 = (const float*)d_in[7];
    const float* b0hh1 = (const float*)d_in[8];
    const float* w1ih0 = (const float*)d_in[9];
    const float* w1hh0 = (const float*)d_in[10];
    const float* b1ih0 = (const float*)d_in[11];
    const float* b1hh0 = (const float*)d_in[12];
    const float* w1ih1 = (const float*)d_in[13];
    const float* w1hh1 = (const float*)d_in[14];
    const float* b1ih1 = (const float*)d_in[15];
    const float* b1hh1 = (const float*)d_in[16];
    const float* Wp    = (const float*)d_in[17];
    const float* bp    = (const float*)d_in[18];
    const float* WH    = (const float*)d_in[19];
    const float* bH    = (const float*)d_in[20];
    const float* WL    = (const float*)d_in[21];
    const float* bL    = (const float*)d_in[22];
    const float* W1    = (const float*)d_in[23];
    const float* b1    = (const float*)d_in[24];
    const float* W2    = (const float*)d_in[25];
    const float* b2    = (const float*)d_in[26];
    const float* W3    = (const float*)d_in[27];
    const float* b3    = (const float*)d_in[28];
    float* out = (float*)d_out;

    prep_u_kernel<<<2, 256>>>(Wp, bp, W3, b3);
    prep_w_kernel<<<(204800 + 255) / 256, 256>>>(WH, WL);

    dim3 gl(NBLOCKS, 2);
    lstm_kernel<<<gl, NTHREADS>>>(x,
        w0ih0, w0hh0, b0ih0, b0hh0, w0ih1, w0hh1, b0ih1, b0hh1,
        w1ih0, w1hh0, b1ih0, b1hh0, w1ih1, w1hh1, b1ih1, b1hh1);

    dim3 gf(NBLOCKS, 2, 2);
    feat_kernel<<<gf, NTHREADS>>>(bH, bL);

    combine_kernel<<<BATCH * 4 / NTHREADS, NTHREADS>>>(W1, b1, W2, b2, W3, out);
}